// round 5
// baseline (speedup 1.0000x reference)
#include <cuda_runtime.h>
#include <cuda_bf16.h>

#define U_CNT 50000
#define I_CNT 100000
#define N_CNT 150000
#define D 128
#define NL 3
#define BATCH 4096

// Scratch (device globals: the allowed scratch mechanism)
__device__ float g_ego  [(size_t)N_CNT * D];            // current (unnormalized) ego
__device__ float g_side [(size_t)N_CNT * D];            // SpMM accumulator
__device__ float g_final[(size_t)N_CNT * D * (NL + 1)]; // [N, 512] concat
__device__ float g_acc[2];                              // bpr sum, reg sum

// ---------------------------------------------------------------------------
// init: ego = concat(user_emb, item_emb); final[:, :128] = ego; side = 0
// ---------------------------------------------------------------------------
__global__ void init_kernel(const float* __restrict__ ue, const float* __restrict__ ie) {
    size_t i = (size_t)blockIdx.x * blockDim.x + threadIdx.x;  // float4 index
    if (i == 0) { g_acc[0] = 0.f; g_acc[1] = 0.f; }
    if (i >= (size_t)N_CNT * (D / 4)) return;
    size_t row = i >> 5;
    int    c4  = (int)(i & 31);
    float4 v;
    if (row < U_CNT) v = ((const float4*)ue)[row * (D / 4) + c4];
    else             v = ((const float4*)ie)[(row - U_CNT) * (D / 4) + c4];
    ((float4*)g_ego)[i]  = v;
    ((float4*)g_side)[i] = make_float4(0.f, 0.f, 0.f, 0.f);
    ((float4*)(g_final + row * (size_t)(D * (NL + 1))))[c4] = v;
}

// ---------------------------------------------------------------------------
// spmm: side[row] += val * ego[col]   (one warp per edge, red.global v4)
// ---------------------------------------------------------------------------
__global__ void spmm_kernel(const int* __restrict__ erow, const int* __restrict__ ecol,
                            const float* __restrict__ eval, int nnz) {
    int lane  = threadIdx.x & 31;
    int warp  = (blockIdx.x * blockDim.x + threadIdx.x) >> 5;
    int nwarp = (gridDim.x * blockDim.x) >> 5;
    for (int e = warp; e < nnz; e += nwarp) {
        int   r = erow[e];
        int   c = ecol[e];
        float v = eval[e];
        float4 x = ((const float4*)(g_ego + (size_t)c * D))[lane];
        x.x *= v; x.y *= v; x.z *= v; x.w *= v;
        float4* dst = ((float4*)(g_side + (size_t)r * D)) + lane;
        unsigned long long p = (unsigned long long)__cvta_generic_to_global(dst);
        asm volatile("red.global.add.v4.f32 [%0], {%1,%2,%3,%4};"
                     :: "l"(p), "f"(x.x), "f"(x.y), "f"(x.z), "f"(x.w)
                     : "memory");
    }
}

// ---------------------------------------------------------------------------
// transform: ego' = lrelu(side@Wg + (ego*side)@Wb + bg + bb)
//            final[:, (l+1)*128:] = ego'/||ego'||; side = 0
// 64 rows/block, 256 threads: thread(cg in [0,32), rg in [0,8)) owns
// rows rg*8..rg*8+7 and cols cg*4..cg*4+3.
// ---------------------------------------------------------------------------
__global__ void __launch_bounds__(256) transform_kernel(
    const float* __restrict__ Wg, const float* __restrict__ Wb,
    const float* __restrict__ bg, const float* __restrict__ bb, int lplus1) {
    __shared__ float s_side[64 * D];
    __shared__ float s_prod[64 * D];
    const int row0 = blockIdx.x * 64;
    const int tid  = threadIdx.x;

    // stage side + ego*side tiles
    for (int i = tid; i < 64 * (D / 4); i += 256) {
        int r  = i >> 5;
        int c4 = i & 31;
        int gr = row0 + r;
        float4 sd = make_float4(0.f, 0.f, 0.f, 0.f);
        float4 eg = sd;
        if (gr < N_CNT) {
            sd = ((const float4*)(g_side + (size_t)gr * D))[c4];
            eg = ((const float4*)(g_ego  + (size_t)gr * D))[c4];
        }
        ((float4*)s_side)[i] = sd;
        ((float4*)s_prod)[i] = make_float4(sd.x * eg.x, sd.y * eg.y, sd.z * eg.z, sd.w * eg.w);
    }
    __syncthreads();

    const int cg = tid & 31;
    const int rg = tid >> 5;

    float acc[8][4];
#pragma unroll
    for (int r = 0; r < 8; r++)
#pragma unroll
        for (int c = 0; c < 4; c++) acc[r][c] = 0.f;

#pragma unroll 1
    for (int k4 = 0; k4 < 32; k4++) {
        float wg[4][4], wb[4][4];
#pragma unroll
        for (int kk = 0; kk < 4; kk++) {
            float4 a = __ldg(((const float4*)(Wg + (size_t)(k4 * 4 + kk) * D)) + cg);
            wg[kk][0] = a.x; wg[kk][1] = a.y; wg[kk][2] = a.z; wg[kk][3] = a.w;
            float4 b = __ldg(((const float4*)(Wb + (size_t)(k4 * 4 + kk) * D)) + cg);
            wb[kk][0] = b.x; wb[kk][1] = b.y; wb[kk][2] = b.z; wb[kk][3] = b.w;
        }
#pragma unroll
        for (int r = 0; r < 8; r++) {
            const int lr = rg * 8 + r;
            float4 sv4 = ((const float4*)(s_side + lr * D))[k4];
            float4 pv4 = ((const float4*)(s_prod + lr * D))[k4];
            float sv[4] = {sv4.x, sv4.y, sv4.z, sv4.w};
            float pv[4] = {pv4.x, pv4.y, pv4.z, pv4.w};
#pragma unroll
            for (int kk = 0; kk < 4; kk++)
#pragma unroll
                for (int c = 0; c < 4; c++)
                    acc[r][c] += sv[kk] * wg[kk][c] + pv[kk] * wb[kk][c];
        }
    }

    float bias[4];
    {
        float4 a = __ldg(((const float4*)bg) + cg);
        float4 b = __ldg(((const float4*)bb) + cg);
        bias[0] = a.x + b.x; bias[1] = a.y + b.y;
        bias[2] = a.z + b.z; bias[3] = a.w + b.w;
    }

#pragma unroll
    for (int r = 0; r < 8; r++) {
        int gr = row0 + rg * 8 + r;
        float v[4];
        float ss = 0.f;
#pragma unroll
        for (int c = 0; c < 4; c++) {
            float x = acc[r][c] + bias[c];
            x = (x >= 0.f) ? x : 0.2f * x;
            v[c] = x;
            ss += x * x;
        }
#pragma unroll
        for (int off = 16; off; off >>= 1) ss += __shfl_xor_sync(0xffffffffu, ss, off);
        float inv = 1.0f / fmaxf(sqrtf(ss), 1e-12f);
        if (gr < N_CNT) {
            ((float4*)(g_ego  + (size_t)gr * D))[cg] = make_float4(v[0], v[1], v[2], v[3]);
            ((float4*)(g_side + (size_t)gr * D))[cg] = make_float4(0.f, 0.f, 0.f, 0.f);
            ((float4*)(g_final + (size_t)gr * (D * (NL + 1)) + (size_t)lplus1 * D))[cg] =
                make_float4(v[0] * inv, v[1] * inv, v[2] * inv, v[3] * inv);
        }
    }
}

// ---------------------------------------------------------------------------
// loss: one warp per batch sample
// ---------------------------------------------------------------------------
__global__ void loss_kernel(const int* __restrict__ user, const int* __restrict__ pos,
                            const int* __restrict__ neg, const float* __restrict__ item_emb) {
    int lane = threadIdx.x & 31;
    int warp = (blockIdx.x * blockDim.x + threadIdx.x) >> 5;
    if (warp >= BATCH) return;
    const int FW = D * (NL + 1);  // 512
    size_t ur = (size_t)user[warp];
    size_t pr = (size_t)U_CNT + pos[warp];
    size_t nr = (size_t)U_CNT + neg[warp];
    const float4* u4 = (const float4*)(g_final + ur * FW);
    const float4* p4 = (const float4*)(g_final + pr * FW);
    const float4* n4 = (const float4*)(g_final + nr * FW);
    float ps = 0.f, ns = 0.f;
#pragma unroll
    for (int t = 0; t < 4; t++) {
        float4 u = u4[lane + 32 * t];
        float4 p = p4[lane + 32 * t];
        float4 n = n4[lane + 32 * t];
        ps += u.x * p.x + u.y * p.y + u.z * p.z + u.w * p.w;
        ns += u.x * n.x + u.y * n.y + u.z * n.z + u.w * n.w;
    }
    float4 a = ((const float4*)(item_emb + (size_t)pos[warp] * D))[lane];
    float4 b = ((const float4*)(item_emb + (size_t)neg[warp] * D))[lane];
    float rs = a.x * a.x + a.y * a.y + a.z * a.z + a.w * a.w
             + b.x * b.x + b.y * b.y + b.z * b.z + b.w * b.w;
#pragma unroll
    for (int off = 16; off; off >>= 1) {
        ps += __shfl_xor_sync(0xffffffffu, ps, off);
        ns += __shfl_xor_sync(0xffffffffu, ns, off);
        rs += __shfl_xor_sync(0xffffffffu, rs, off);
    }
    if (lane == 0) {
        float x  = ns - ps;
        float sp = fmaxf(x, 0.f) + log1pf(expf(-fabsf(x)));
        atomicAdd(&g_acc[0], sp);
        atomicAdd(&g_acc[1], rs);
    }
}

__global__ void finalize_kernel(float* __restrict__ out) {
    out[0] = g_acc[0] / (float)BATCH;
    out[1] = 1e-4f * 0.5f * g_acc[1] / (float)BATCH;
}

// ---------------------------------------------------------------------------
extern "C" void kernel_launch(void* const* d_in, const int* in_sizes, int n_in,
                              void* d_out, int out_size) {
    const int*   user = (const int*)d_in[0];
    const int*   pos  = (const int*)d_in[1];
    const int*   neg  = (const int*)d_in[2];
    const int*   erow = (const int*)d_in[3];
    const int*   ecol = (const int*)d_in[4];
    const float* evalp = (const float*)d_in[5];
    const float* ue   = (const float*)d_in[6];
    const float* ie   = (const float*)d_in[7];
    const float* Wg   = (const float*)d_in[8];
    const float* bg   = (const float*)d_in[9];
    const float* Wb   = (const float*)d_in[10];
    const float* bb   = (const float*)d_in[11];
    float* out = (float*)d_out;
    int nnz = in_sizes[3];

    {
        int total = N_CNT * (D / 4);
        init_kernel<<<(total + 255) / 256, 256>>>(ue, ie);
    }
    for (int l = 0; l < NL; l++) {
        {
            long long threads = (long long)nnz * 32;
            int blocks = (int)((threads + 255) / 256);
            spmm_kernel<<<blocks, 256>>>(erow, ecol, evalp, nnz);
        }
        transform_kernel<<<(N_CNT + 63) / 64, 256>>>(
            Wg + (size_t)l * D * D, Wb + (size_t)l * D * D,
            bg + (size_t)l * D,     bb + (size_t)l * D, l + 1);
    }
    loss_kernel<<<(BATCH * 32 + 255) / 256, 256>>>(user, pos, neg, ie);
    finalize_kernel<<<1, 1>>>(out);
}

// round 8
// speedup vs baseline: 1.9197x; 1.9197x over previous
#include <cuda_runtime.h>
#include <cuda_bf16.h>

#define U_CNT 50000
#define I_CNT 100000
#define N_CNT 150000
#define D 128
#define NL 3
#define BATCH 4096
#define MAXE 4800000
#define SCAN_ELEMS 2048
#define SCAN_BLOCKS ((N_CNT + SCAN_ELEMS - 1) / SCAN_ELEMS)   // 74

// Scratch (device globals: the allowed scratch mechanism)
__device__ float g_ego  [(size_t)N_CNT * D];            // current (unnormalized) ego
__device__ float g_side [(size_t)N_CNT * D];            // SpMM output
__device__ float g_final[(size_t)N_CNT * D * (NL + 1)]; // [N, 512] concat
__device__ float g_acc[2];                              // bpr sum, reg sum
// CSR-by-row edge structure, rebuilt each launch
__device__ int   g_cnt[N_CNT];        // histogram -> running cursor
__device__ int   g_off[N_CNT + 1];    // row offsets
__device__ int   g_bsum[SCAN_BLOCKS]; // scan block sums
__device__ int2  g_sedge[MAXE];       // (col, val-as-bits), row-sorted

// ---------------------------------------------------------------------------
// init: ego = concat(user_emb, item_emb); final[:, :128] = ego; cnt = 0
// ---------------------------------------------------------------------------
__global__ void init_kernel(const float* __restrict__ ue, const float* __restrict__ ie) {
    size_t i = (size_t)blockIdx.x * blockDim.x + threadIdx.x;  // float4 index
    if (i == 0) { g_acc[0] = 0.f; g_acc[1] = 0.f; }
    if (i >= (size_t)N_CNT * (D / 4)) return;
    size_t row = i >> 5;
    int    c4  = (int)(i & 31);
    if (c4 == 0) g_cnt[row] = 0;
    float4 v;
    if (row < U_CNT) v = ((const float4*)ue)[row * (D / 4) + c4];
    else             v = ((const float4*)ie)[(row - U_CNT) * (D / 4) + c4];
    ((float4*)g_ego)[i] = v;
    ((float4*)(g_final + row * (size_t)(D * (NL + 1))))[c4] = v;
}

// ---------------------------------------------------------------------------
// CSR build: histogram -> 3-phase exclusive scan -> scatter
// ---------------------------------------------------------------------------
__global__ void hist_kernel(const int* __restrict__ erow, int nnz) {
    int e = blockIdx.x * blockDim.x + threadIdx.x;
    if (e < nnz) atomicAdd(&g_cnt[erow[e]], 1);
}

__global__ void __launch_bounds__(256) scan1_kernel() {
    __shared__ int s_warp[8];
    int b = blockIdx.x, t = threadIdx.x;
    int lane = t & 31, wid = t >> 5;
    int base = b * SCAN_ELEMS + t * 8;
    int v[8], tot = 0;
#pragma unroll
    for (int j = 0; j < 8; j++) {
        int idx = base + j;
        v[j] = (idx < N_CNT) ? g_cnt[idx] : 0;
        tot += v[j];
    }
    int inc = tot;
#pragma unroll
    for (int off = 1; off < 32; off <<= 1) {
        int y = __shfl_up_sync(0xffffffffu, inc, off);
        if (lane >= off) inc += y;
    }
    if (lane == 31) s_warp[wid] = inc;
    __syncthreads();
    if (t < 8) {
        int w = s_warp[t];
        int winc = w;
#pragma unroll
        for (int off = 1; off < 8; off <<= 1) {
            int y = __shfl_up_sync(0xffu, winc, off);
            if (t >= off) winc += y;
        }
        s_warp[t] = winc - w;  // exclusive warp prefix
    }
    __syncthreads();
    int run = inc - tot + s_warp[wid];  // exclusive thread prefix in block
    if (t == 255) g_bsum[b] = run + tot;
#pragma unroll
    for (int j = 0; j < 8; j++) {
        int idx = base + j;
        if (idx < N_CNT) g_off[idx] = run;
        run += v[j];
    }
}

__global__ void scan2_kernel() {
    __shared__ int s_warp[4];
    int t = threadIdx.x, lane = t & 31, wid = t >> 5;
    int x = (t < SCAN_BLOCKS) ? g_bsum[t] : 0;
    int inc = x;
#pragma unroll
    for (int off = 1; off < 32; off <<= 1) {
        int y = __shfl_up_sync(0xffffffffu, inc, off);
        if (lane >= off) inc += y;
    }
    if (lane == 31) s_warp[wid] = inc;
    __syncthreads();
    if (t < 4) {
        int w = s_warp[t];
        int winc = w;
#pragma unroll
        for (int off = 1; off < 4; off <<= 1) {
            int y = __shfl_up_sync(0xfu, winc, off);
            if (t >= off) winc += y;
        }
        s_warp[t] = winc - w;
    }
    __syncthreads();
    if (t < SCAN_BLOCKS) g_bsum[t] = inc - x + s_warp[wid];
}

__global__ void scan3_kernel(int nnz) {
    int i = blockIdx.x * blockDim.x + threadIdx.x;
    if (i == 0) g_off[N_CNT] = nnz;
    if (i >= N_CNT) return;
    int o = g_off[i] + g_bsum[i >> 11];  // SCAN_ELEMS = 2048
    g_off[i] = o;
    g_cnt[i] = o;  // cursor for scatter
}

__global__ void scatter_kernel(const int* __restrict__ erow, const int* __restrict__ ecol,
                               const float* __restrict__ ev, int nnz) {
    int e = blockIdx.x * blockDim.x + threadIdx.x;
    if (e >= nnz) return;
    int r = erow[e];
    int pos = atomicAdd(&g_cnt[r], 1);
    g_sedge[pos] = make_int2(ecol[e], __float_as_int(ev[e]));
}

// ---------------------------------------------------------------------------
// spmm (CSR): one warp per row, register accumulation, no atomics
// ---------------------------------------------------------------------------
__global__ void __launch_bounds__(256) spmm_csr_kernel() {
    int lane = threadIdx.x & 31;
    int row  = (blockIdx.x * blockDim.x + threadIdx.x) >> 5;
    if (row >= N_CNT) return;
    int s = __ldg(&g_off[row]);
    int e = __ldg(&g_off[row + 1]);
    float4 acc = make_float4(0.f, 0.f, 0.f, 0.f);
    for (int base = s; base < e; base += 32) {
        int n = min(32, e - base);
        int2 ed = (lane < n) ? g_sedge[base + lane] : make_int2(0, 0);
        for (int j = 0; j < n; j++) {
            int   col = __shfl_sync(0xffffffffu, ed.x, j);
            float v   = __int_as_float(__shfl_sync(0xffffffffu, ed.y, j));
            float4 x = __ldg(((const float4*)(g_ego + (size_t)col * D)) + lane);
            acc.x += v * x.x; acc.y += v * x.y;
            acc.z += v * x.z; acc.w += v * x.w;
        }
    }
    __stcs(((float4*)(g_side + (size_t)row * D)) + lane, acc);
}

// ---------------------------------------------------------------------------
// transform: ego' = lrelu(side@Wg + (ego*side)@Wb + bg + bb)
//            final[:, (l+1)*128:] = ego'/||ego'||
// ---------------------------------------------------------------------------
__global__ void __launch_bounds__(256) transform_kernel(
    const float* __restrict__ Wg, const float* __restrict__ Wb,
    const float* __restrict__ bg, const float* __restrict__ bb,
    int lplus1, int write_ego) {
    __shared__ float s_side[64 * D];
    __shared__ float s_prod[64 * D];
    const int row0 = blockIdx.x * 64;
    const int tid  = threadIdx.x;

    for (int i = tid; i < 64 * (D / 4); i += 256) {
        int r  = i >> 5;
        int c4 = i & 31;
        int gr = row0 + r;
        float4 sd = make_float4(0.f, 0.f, 0.f, 0.f);
        float4 eg = sd;
        if (gr < N_CNT) {
            sd = __ldcs(((const float4*)(g_side + (size_t)gr * D)) + c4);
            eg = ((const float4*)(g_ego  + (size_t)gr * D))[c4];
        }
        ((float4*)s_side)[i] = sd;
        ((float4*)s_prod)[i] = make_float4(sd.x * eg.x, sd.y * eg.y, sd.z * eg.z, sd.w * eg.w);
    }
    __syncthreads();

    const int cg = tid & 31;
    const int rg = tid >> 5;

    float acc[8][4];
#pragma unroll
    for (int r = 0; r < 8; r++)
#pragma unroll
        for (int c = 0; c < 4; c++) acc[r][c] = 0.f;

#pragma unroll 1
    for (int k4 = 0; k4 < 32; k4++) {
        float wg[4][4], wb[4][4];
#pragma unroll
        for (int kk = 0; kk < 4; kk++) {
            float4 a = __ldg(((const float4*)(Wg + (size_t)(k4 * 4 + kk) * D)) + cg);
            wg[kk][0] = a.x; wg[kk][1] = a.y; wg[kk][2] = a.z; wg[kk][3] = a.w;
            float4 b = __ldg(((const float4*)(Wb + (size_t)(k4 * 4 + kk) * D)) + cg);
            wb[kk][0] = b.x; wb[kk][1] = b.y; wb[kk][2] = b.z; wb[kk][3] = b.w;
        }
#pragma unroll
        for (int r = 0; r < 8; r++) {
            const int lr = rg * 8 + r;
            float4 sv4 = ((const float4*)(s_side + lr * D))[k4];
            float4 pv4 = ((const float4*)(s_prod + lr * D))[k4];
            float sv[4] = {sv4.x, sv4.y, sv4.z, sv4.w};
            float pv[4] = {pv4.x, pv4.y, pv4.z, pv4.w};
#pragma unroll
            for (int kk = 0; kk < 4; kk++)
#pragma unroll
                for (int c = 0; c < 4; c++)
                    acc[r][c] += sv[kk] * wg[kk][c] + pv[kk] * wb[kk][c];
        }
    }

    float bias[4];
    {
        float4 a = __ldg(((const float4*)bg) + cg);
        float4 b = __ldg(((const float4*)bb) + cg);
        bias[0] = a.x + b.x; bias[1] = a.y + b.y;
        bias[2] = a.z + b.z; bias[3] = a.w + b.w;
    }

#pragma unroll
    for (int r = 0; r < 8; r++) {
        int gr = row0 + rg * 8 + r;
        float v[4];
        float ss = 0.f;
#pragma unroll
        for (int c = 0; c < 4; c++) {
            float x = acc[r][c] + bias[c];
            x = (x >= 0.f) ? x : 0.2f * x;
            v[c] = x;
            ss += x * x;
        }
#pragma unroll
        for (int off = 16; off; off >>= 1) ss += __shfl_xor_sync(0xffffffffu, ss, off);
        float inv = 1.0f / fmaxf(sqrtf(ss), 1e-12f);
        if (gr < N_CNT) {
            if (write_ego)
                ((float4*)(g_ego + (size_t)gr * D))[cg] = make_float4(v[0], v[1], v[2], v[3]);
            __stcs(((float4*)(g_final + (size_t)gr * (D * (NL + 1)) + (size_t)lplus1 * D)) + cg,
                   make_float4(v[0] * inv, v[1] * inv, v[2] * inv, v[3] * inv));
        }
    }
}

// ---------------------------------------------------------------------------
// loss: one warp per batch sample
// ---------------------------------------------------------------------------
__global__ void loss_kernel(const int* __restrict__ user, const int* __restrict__ pos,
                            const int* __restrict__ neg, const float* __restrict__ item_emb) {
    int lane = threadIdx.x & 31;
    int warp = (blockIdx.x * blockDim.x + threadIdx.x) >> 5;
    if (warp >= BATCH) return;
    const int FW = D * (NL + 1);  // 512
    size_t ur = (size_t)user[warp];
    size_t pr = (size_t)U_CNT + pos[warp];
    size_t nr = (size_t)U_CNT + neg[warp];
    const float4* u4 = (const float4*)(g_final + ur * FW);
    const float4* p4 = (const float4*)(g_final + pr * FW);
    const float4* n4 = (const float4*)(g_final + nr * FW);
    float ps = 0.f, ns = 0.f;
#pragma unroll
    for (int t = 0; t < 4; t++) {
        float4 u = u4[lane + 32 * t];
        float4 p = p4[lane + 32 * t];
        float4 n = n4[lane + 32 * t];
        ps += u.x * p.x + u.y * p.y + u.z * p.z + u.w * p.w;
        ns += u.x * n.x + u.y * n.y + u.z * n.z + u.w * n.w;
    }
    float4 a = ((const float4*)(item_emb + (size_t)pos[warp] * D))[lane];
    float4 b = ((const float4*)(item_emb + (size_t)neg[warp] * D))[lane];
    float rs = a.x * a.x + a.y * a.y + a.z * a.z + a.w * a.w
             + b.x * b.x + b.y * b.y + b.z * b.z + b.w * b.w;
#pragma unroll
    for (int off = 16; off; off >>= 1) {
        ps += __shfl_xor_sync(0xffffffffu, ps, off);
        ns += __shfl_xor_sync(0xffffffffu, ns, off);
        rs += __shfl_xor_sync(0xffffffffu, rs, off);
    }
    if (lane == 0) {
        float x  = ns - ps;
        float sp = fmaxf(x, 0.f) + log1pf(expf(-fabsf(x)));
        atomicAdd(&g_acc[0], sp);
        atomicAdd(&g_acc[1], rs);
    }
}

__global__ void finalize_kernel(float* __restrict__ out) {
    out[0] = g_acc[0] / (float)BATCH;
    out[1] = 1e-4f * 0.5f * g_acc[1] / (float)BATCH;
}

// ---------------------------------------------------------------------------
extern "C" void kernel_launch(void* const* d_in, const int* in_sizes, int n_in,
                              void* d_out, int out_size) {
    const int*   user = (const int*)d_in[0];
    const int*   pos  = (const int*)d_in[1];
    const int*   neg  = (const int*)d_in[2];
    const int*   erow = (const int*)d_in[3];
    const int*   ecol = (const int*)d_in[4];
    const float* evalp = (const float*)d_in[5];
    const float* ue   = (const float*)d_in[6];
    const float* ie   = (const float*)d_in[7];
    const float* Wg   = (const float*)d_in[8];
    const float* bg   = (const float*)d_in[9];
    const float* Wb   = (const float*)d_in[10];
    const float* bb   = (const float*)d_in[11];
    float* out = (float*)d_out;
    int nnz = in_sizes[3];
    if (nnz > MAXE) nnz = MAXE;

    {
        int total = N_CNT * (D / 4);
        init_kernel<<<(total + 255) / 256, 256>>>(ue, ie);
    }
    // Build row-sorted CSR once, reused by all 3 layers
    hist_kernel<<<(nnz + 255) / 256, 256>>>(erow, nnz);
    scan1_kernel<<<SCAN_BLOCKS, 256>>>();
    scan2_kernel<<<1, 128>>>();
    scan3_kernel<<<(N_CNT + 255) / 256, 256>>>(nnz);
    scatter_kernel<<<(nnz + 255) / 256, 256>>>(erow, ecol, evalp, nnz);

    for (int l = 0; l < NL; l++) {
        spmm_csr_kernel<<<(N_CNT * 32 + 255) / 256, 256>>>();
        transform_kernel<<<(N_CNT + 63) / 64, 256>>>(
            Wg + (size_t)l * D * D, Wb + (size_t)l * D * D,
            bg + (size_t)l * D,     bb + (size_t)l * D,
            l + 1, (l < NL - 1) ? 1 : 0);
    }
    loss_kernel<<<(BATCH * 32 + 255) / 256, 256>>>(user, pos, neg, ie);
    finalize_kernel<<<1, 1>>>(out);
}